// round 15
// baseline (speedup 1.0000x reference)
#include <cuda_runtime.h>
#include <cuda_fp16.h>
#include <math.h>
#include <stdint.h>

#define Bm 4
#define Tt 2048
#define Cc 1024
#define Hh 16
#define Dd 64
#define Mrows (Bm*Tt)   // 8192

// ------------------------- device-global scratch (fp16) ---------------------
__device__ __half g_qh[Bm*Hh*Tt*Dd];  // [B,H,T,D] hi (pre-scaled 1/8), no lo
__device__ __half g_kh[Bm*Hh*Tt*Dd];
__device__ __half g_kl[Bm*Hh*Tt*Dd];
__device__ __half g_vh[Bm*Hh*Tt*Dd];
__device__ __half g_vl[Bm*Hh*Tt*Dd];

__device__ __half g_xh[Mrows*Cc];
__device__ __half g_yh[Mrows*Cc];      // attention output (hi only)
__device__ __half g_wh[4*Cc*Cc];
__device__ __half g_wl[4*Cc*Cc];

// ---------------------------------------------------------------------------
// fused split kernel: x -> fp16 hi only; weights -> fp16 hi + lo
// ---------------------------------------------------------------------------
__global__ void split_all(const float* __restrict__ x,
                          const float* __restrict__ Wq, const float* __restrict__ Wk,
                          const float* __restrict__ Wv, const float* __restrict__ Wp)
{
    const int bi = blockIdx.x;
    const int tid = threadIdx.x;

    if (bi < 8192) {
        int i = (bi * 256 + tid) * 4;
        float4 v = *(const float4*)(x + i);
        __half2 a; a.x = __float2half_rn(v.x); a.y = __float2half_rn(v.y);
        __half2 b; b.x = __float2half_rn(v.z); b.y = __float2half_rn(v.w);
        *(uint32_t*)(g_xh + i)     = *(uint32_t*)&a;
        *(uint32_t*)(g_xh + i + 2) = *(uint32_t*)&b;
        return;
    }

    int r = bi - 8192;
    int which = r >> 10;
    const float* src = (which == 0) ? Wq : (which == 1) ? Wk : (which == 2) ? Wv : Wp;
    __half* hi = g_wh + (size_t)which * Cc * Cc;
    __half* lo = g_wl + (size_t)which * Cc * Cc;
    int i = (((r & 1023) * 256) + tid) * 4;

    float4 v = *(const float4*)(src + i);
    __half h0 = __float2half_rn(v.x);
    __half h1 = __float2half_rn(v.y);
    __half h2 = __float2half_rn(v.z);
    __half h3 = __float2half_rn(v.w);
    hi[i+0] = h0; hi[i+1] = h1; hi[i+2] = h2; hi[i+3] = h3;
    lo[i+0] = __float2half_rn(v.x - __half2float(h0));
    lo[i+1] = __float2half_rn(v.y - __half2float(h1));
    lo[i+2] = __float2half_rn(v.z - __half2float(h2));
    lo[i+3] = __float2half_rn(v.w - __half2float(h3));
}

// ---------------------------------------------------------------------------
// helpers
// ---------------------------------------------------------------------------
__device__ __forceinline__ uint32_t sptr(const void* p)
{ uint32_t a; asm("{ .reg .u64 t; cvta.to.shared.u64 t, %1; cvt.u32.u64 %0, t; }" : "=r"(a) : "l"(p)); return a; }

__device__ __forceinline__ uint32_t pk(float a, float b)
{
    __half2 t = __floats2half2_rn(a, b);   // a -> low half
    return *(uint32_t*)&t;
}

__device__ __forceinline__ void mma16816(float* c, const uint32_t* a, const uint32_t* b)
{
    asm volatile(
        "mma.sync.aligned.m16n8k16.row.col.f32.f16.f16.f32 "
        "{%0,%1,%2,%3}, {%4,%5,%6,%7}, {%8,%9}, {%0,%1,%2,%3};\n"
        : "+f"(c[0]), "+f"(c[1]), "+f"(c[2]), "+f"(c[3])
        : "r"(a[0]), "r"(a[1]), "r"(a[2]), "r"(a[3]), "r"(b[0]), "r"(b[1]));
}
__device__ __forceinline__ void ldm4(uint32_t* r, uint32_t a)
{
    asm volatile("ldmatrix.sync.aligned.m8n8.x4.shared.b16 {%0,%1,%2,%3}, [%4];"
        : "=r"(r[0]), "=r"(r[1]), "=r"(r[2]), "=r"(r[3]) : "r"(a));
}
__device__ __forceinline__ void ldm4t(uint32_t* r, uint32_t a)
{
    asm volatile("ldmatrix.sync.aligned.m8n8.x4.trans.shared.b16 {%0,%1,%2,%3}, [%4];"
        : "=r"(r[0]), "=r"(r[1]), "=r"(r[2]), "=r"(r[3]) : "r"(a));
}

__device__ __forceinline__ void cpa16(uint32_t dst, const void* src)
{ asm volatile("cp.async.cg.shared.global [%0], [%1], 16;" :: "r"(dst), "l"(src)); }
#define CP_COMMIT() asm volatile("cp.async.commit_group;" ::: "memory")
#define CP_WAIT1()  asm volatile("cp.async.wait_group 1;" ::: "memory")
#define CP_WAIT0()  asm volatile("cp.async.wait_group 0;" ::: "memory")

// ---------------------------------------------------------------------------
// 2-term split-fp16 GEMM: C = Ah @ (Wh + Wl)^T + bias.
// K-stage 32, 3-stage cp.async ring, ldmatrix frags, 2 CTAs/SM.
// MMA order: all h-terms across 4 accs, then all l-terms (RAW distance 4).
// ---------------------------------------------------------------------------
#define PE   40              // pitch in fp16 elements (80 B)
#define STG  30720           // stage bytes (3 arrays x 128 rows x 80 B)
#define G_SMEM (3*STG)       // 92160 B -> 2 CTAs/SM

__global__ __launch_bounds__(256, 2) void gemm_db(
    const __half* __restrict__ Ah,
    const __half* __restrict__ Wh, const __half* __restrict__ Wl,
    const float* __restrict__ b0, const float* __restrict__ b1,
    const float* __restrict__ b2,
    float* __restrict__ outp, int fused)
{
    extern __shared__ char smem[];
    const uint32_t sb = sptr(smem);

    const int which = blockIdx.z;
    const __half* __restrict__ Bh = Wh + (size_t)which * Cc * Cc;
    const __half* __restrict__ Bl = Wl + (size_t)which * Cc * Cc;
    const float* __restrict__ bias = (which == 0) ? b0 : (which == 1) ? b1 : b2;
    const int mode = fused ? which : 3;

    const int tid  = threadIdx.x;
    const int warp = tid >> 5;
    const int lane = tid & 31;
    const int warpM = warp & 3;
    const int warpN = warp >> 2;
    const int gid = lane >> 2;
    const int tig = lane & 3;

    const int rowBase = blockIdx.y * 128;
    const int colBase = blockIdx.x * 128;

    float acc[2][8][4];
    #pragma unroll
    for (int i = 0; i < 2; i++)
        #pragma unroll
        for (int j = 0; j < 8; j++)
            #pragma unroll
            for (int k = 0; k < 4; k++) acc[i][j][k] = 0.0f;

    auto issue = [&](int s, int buf) {
        const int k0 = s * 32;
        const uint32_t bb = sb + buf * STG;
        #pragma unroll
        for (int t = 0; t < 6; t++) {
            int idx = tid + t * 256;
            int row = idx >> 2;
            int part = idx & 3;
            int arr = row >> 7;               // 0:Ah 1:Bh 2:Bl
            int r = row & 127;
            const __half* src = (arr == 0) ? Ah : (arr == 1) ? Bh : Bl;
            int grow = (arr == 0) ? (rowBase + r) : (colBase + r);
            cpa16(bb + arr * 10240 + r * 80 + part * 16,
                  src + (size_t)grow * Cc + k0 + part * 8);
        }
    };

    issue(0, 0);
    CP_COMMIT();
    issue(1, 1);
    CP_COMMIT();

    int bufs = 0;
    for (int s = 0; s < 32; s++) {
        if (s + 1 < 32) { CP_WAIT1(); } else { CP_WAIT0(); }
        __syncthreads();
        if (s + 2 < 32) {
            int b2i = bufs + 2; if (b2i >= 3) b2i -= 3;
            issue(s + 2, b2i);
            CP_COMMIT();
        }

        const char* bb = smem + bufs * STG;
        const __half* sAh = (const __half*)(bb + 0);
        const __half* sBh = (const __half*)(bb + 10240);
        const __half* sBl = (const __half*)(bb + 20480);

        #pragma unroll
        for (int kg = 0; kg < 2; kg++) {
            const int colE = kg * 16 + (lane >> 4) * 8;
            const int arow = warpM * 32 + (lane & 15);

            uint32_t ah0[4], ah1[4];
            ldm4(ah0, sptr(sAh + arow * PE + colE));
            ldm4(ah1, sptr(sAh + (arow + 16) * PE + colE));

            #pragma unroll
            for (int grp = 0; grp < 4; grp++) {
                const int brow = warpN * 64 + grp * 16 + (lane & 15);
                uint32_t th[4], tl[4];
                ldm4(th, sptr(sBh + brow * PE + colE));
                ldm4(tl, sptr(sBl + brow * PE + colE));
                uint32_t b0h[2] = {th[0], th[2]};
                uint32_t b1h[2] = {th[1], th[3]};
                uint32_t b0l[2] = {tl[0], tl[2]};
                uint32_t b1l[2] = {tl[1], tl[3]};
                const int n0 = 2 * grp, n1 = 2 * grp + 1;

                // h-terms first across the 4 distinct accumulators,
                // then l-terms: same-acc RAW distance 1 -> 4.
                mma16816(acc[0][n0], ah0, b0h);
                mma16816(acc[0][n1], ah0, b1h);
                mma16816(acc[1][n0], ah1, b0h);
                mma16816(acc[1][n1], ah1, b1h);
                mma16816(acc[0][n0], ah0, b0l);
                mma16816(acc[0][n1], ah0, b1l);
                mma16816(acc[1][n0], ah1, b0l);
                mma16816(acc[1][n1], ah1, b1l);
            }
        }
        if (++bufs == 3) bufs = 0;
    }

    // ---- epilogue ----
    if (mode == 3) {
        #pragma unroll
        for (int mi = 0; mi < 2; mi++) {
            #pragma unroll
            for (int ni = 0; ni < 8; ni++) {
                int m0 = rowBase + warpM * 32 + mi * 16 + gid;
                int n0 = colBase + warpN * 64 + ni * 8 + tig * 2;
                #pragma unroll
                for (int e = 0; e < 4; e++) {
                    int m = m0 + ((e >> 1) ? 8 : 0);
                    int n = n0 + (e & 1);
                    outp[(size_t)m * Cc + n] = acc[mi][ni][e] + bias[n];
                }
            }
        }
    } else if (mode == 0) {
        #pragma unroll
        for (int mi = 0; mi < 2; mi++) {
            #pragma unroll
            for (int ni = 0; ni < 8; ni++) {
                int m0 = rowBase + warpM * 32 + mi * 16 + gid;
                int n0 = colBase + warpN * 64 + ni * 8 + tig * 2;
                #pragma unroll
                for (int half = 0; half < 2; half++) {
                    int m = m0 + half * 8;
                    float v0 = (acc[mi][ni][half*2+0] + bias[n0])   * 0.125f;
                    float v1 = (acc[mi][ni][half*2+1] + bias[n0+1]) * 0.125f;
                    int b = m >> 11, t = m & 2047;
                    int h = n0 >> 6, d = n0 & 63;
                    size_t off = (((size_t)(b * Hh + h)) * Tt + t) * Dd + d;
                    *(uint32_t*)(g_qh + off) = pk(v0, v1);
                }
            }
        }
    } else {
        __half* dh = (mode == 1) ? g_kh : g_vh;
        __half* dl = (mode == 1) ? g_kl : g_vl;

        #pragma unroll
        for (int mi = 0; mi < 2; mi++) {
            #pragma unroll
            for (int ni = 0; ni < 8; ni++) {
                int m0 = rowBase + warpM * 32 + mi * 16 + gid;
                int n0 = colBase + warpN * 64 + ni * 8 + tig * 2;
                #pragma unroll
                for (int half = 0; half < 2; half++) {
                    int m = m0 + half * 8;
                    float v0 = acc[mi][ni][half*2+0] + bias[n0];
                    float v1 = acc[mi][ni][half*2+1] + bias[n0+1];
                    __half h0 = __float2half_rn(v0);
                    __half h1 = __float2half_rn(v1);
                    int b = m >> 11, t = m & 2047;
                    int h = n0 >> 6, d = n0 & 63;
                    size_t off = (((size_t)(b * Hh + h)) * Tt + t) * Dd + d;
                    __half2 hp; hp.x = h0; hp.y = h1;
                    *(uint32_t*)(dh + off) = *(uint32_t*)&hp;
                    *(uint32_t*)(dl + off) = pk(v0 - __half2float(h0),
                                                v1 - __half2float(h1));
                }
            }
        }
    }
}

// ---------------------------------------------------------------------------
// Flash attention, 2-term fp16, causal, cp.async double-buffer, 2 CTAs/SM.
// MMA order in S and PV loops: h-terms across all accumulators first, then
// l-terms (same-acc RAW distance 8).
// ---------------------------------------------------------------------------
#define ABUFSZ 36864
#define ATT_ARR (64*72*2)     // 9216 B per array

__global__ __launch_bounds__(256, 2) void attn_mma()
{
    extern __shared__ char sm[];
    const uint32_t sbase = sptr(sm);

    const int bh = blockIdx.y;
    const int qblk = (int)gridDim.x - 1 - (int)blockIdx.x;
    const int tid = threadIdx.x;
    const int warp = tid >> 5;
    const int lane = tid & 31;
    const int g = lane >> 2;
    const int tig = lane & 3;

    const size_t base = (size_t)bh * Tt * Dd;

    // ---- stage Q tile (hi only, 128 rows x 64 cols) into buf0 ----
    {
        __half* sQh = (__half*)sm;
        #pragma unroll
        for (int it = 0; it < 4; it++) {
            int idx = tid + it * 256;
            int r = idx >> 3, c8 = (idx & 7) * 8;
            size_t goff = base + (size_t)(qblk*128 + r) * Dd + c8;
            *(uint4*)(sQh + r*72 + c8) = *(const uint4*)(g_qh + goff);
        }
    }
    __syncthreads();

    uint32_t qfh[4][4];
    {
        __half* sQh = (__half*)sm;
        int row = warp*16 + (lane & 15);
        #pragma unroll
        for (int kt = 0; kt < 4; kt++) {
            int col = kt*16 + (lane >> 4) * 8;
            ldm4(qfh[kt], sptr(sQh + row*72 + col));
        }
    }
    __syncthreads();

    float o[8][4];
    #pragma unroll
    for (int i = 0; i < 8; i++)
        #pragma unroll
        for (int j = 0; j < 4; j++) o[i][j] = 0.0f;

    float mA = -INFINITY, mB = -INFINITY, lA = 0.0f, lB = 0.0f;
    const int wr0 = qblk*128 + warp*16;
    const int ntiles = 2*qblk + 2;

    auto load_kv = [&](int kb, int buf) {
        const uint32_t bb = sbase + buf * ABUFSZ;
        #pragma unroll
        for (int it = 0; it < 2; it++) {
            int idx = tid + it * 256;
            int r = idx >> 3, c8 = (idx & 7) * 8;
            size_t goff = base + (size_t)(kb + r) * Dd + c8;
            uint32_t so = (r*72 + c8) * 2;
            cpa16(bb + 0*ATT_ARR + so, g_kh + goff);
            cpa16(bb + 1*ATT_ARR + so, g_kl + goff);
            cpa16(bb + 2*ATT_ARR + so, g_vh + goff);
            cpa16(bb + 3*ATT_ARR + so, g_vl + goff);
        }
    };

    load_kv(0, 0);
    CP_COMMIT();

    for (int ti = 0; ti < ntiles; ti++) {
        const int kb = ti * 64;
        CP_WAIT0();
        __syncthreads();
        if (ti + 1 < ntiles) { load_kv(kb + 64, (ti + 1) & 1); CP_COMMIT(); }

        const char* bb = sm + (ti & 1) * ABUFSZ;
        const __half* sKh = (const __half*)(bb + 0*ATT_ARR);
        const __half* sKl = (const __half*)(bb + 1*ATT_ARR);
        const __half* sVh = (const __half*)(bb + 2*ATT_ARR);
        const __half* sVl = (const __half*)(bb + 3*ATT_ARR);

        // ---- S = qh (kh + kl)^T (2-term, reordered) ----
        float s[8][4];
        #pragma unroll
        for (int i = 0; i < 8; i++)
            #pragma unroll
            for (int j = 0; j < 4; j++) s[i][j] = 0.0f;

        #pragma unroll
        for (int kt = 0; kt < 4; kt++) {
            uint32_t kh4[4][4], kl4[4][4];
            #pragma unroll
            for (int i = 0; i < 4; i++) {
                int row = i*16 + (lane & 15);
                int col = kt*16 + (lane >> 4) * 8;
                ldm4(kh4[i], sptr(sKh + row*72 + col));
                ldm4(kl4[i], sptr(sKl + row*72 + col));
            }
            // h-terms across all 8 accumulators
            #pragma unroll
            for (int i = 0; i < 4; i++) {
                uint32_t b0h[2] = {kh4[i][0], kh4[i][2]};
                uint32_t b1h[2] = {kh4[i][1], kh4[i][3]};
                mma16816(s[2*i],   qfh[kt], b0h);
                mma16816(s[2*i+1], qfh[kt], b1h);
            }
            // l-terms
            #pragma unroll
            for (int i = 0; i < 4; i++) {
                uint32_t b0l[2] = {kl4[i][0], kl4[i][2]};
                uint32_t b1l[2] = {kl4[i][1], kl4[i][3]};
                mma16816(s[2*i],   qfh[kt], b0l);
                mma16816(s[2*i+1], qfh[kt], b1l);
            }
        }

        // ---- causal mask ----
        if (kb + 64 > wr0) {
            int rA = wr0 + g, rB = rA + 8;
            #pragma unroll
            for (int nt = 0; nt < 8; nt++) {
                int c0 = kb + nt*8 + tig*2;
                if (c0     > rA) s[nt][0] = -INFINITY;
                if (c0 + 1 > rA) s[nt][1] = -INFINITY;
                if (c0     > rB) s[nt][2] = -INFINITY;
                if (c0 + 1 > rB) s[nt][3] = -INFINITY;
            }
        }

        // ---- online softmax ----
        float ma = -INFINITY, mb = -INFINITY;
        #pragma unroll
        for (int nt = 0; nt < 8; nt++) {
            ma = fmaxf(ma, fmaxf(s[nt][0], s[nt][1]));
            mb = fmaxf(mb, fmaxf(s[nt][2], s[nt][3]));
        }
        ma = fmaxf(ma, __shfl_xor_sync(0xffffffff, ma, 1));
        ma = fmaxf(ma, __shfl_xor_sync(0xffffffff, ma, 2));
        mb = fmaxf(mb, __shfl_xor_sync(0xffffffff, mb, 1));
        mb = fmaxf(mb, __shfl_xor_sync(0xffffffff, mb, 2));

        float nmA = fmaxf(mA, ma), nmB = fmaxf(mB, mb);
        float cA = __expf(mA - nmA), cB = __expf(mB - nmB);
        mA = nmA; mB = nmB;
        lA *= cA; lB *= cB;
        #pragma unroll
        for (int nt = 0; nt < 8; nt++) {
            o[nt][0] *= cA; o[nt][1] *= cA;
            o[nt][2] *= cB; o[nt][3] *= cB;
        }

        // ---- p = exp(s - m), fp16 ----
        uint32_t pah[4][4];
        float suA = 0.0f, suB = 0.0f;
        #pragma unroll
        for (int nt = 0; nt < 8; nt++) {
            float p0 = __expf(s[nt][0] - nmA);
            float p1 = __expf(s[nt][1] - nmA);
            float p2 = __expf(s[nt][2] - nmB);
            float p3 = __expf(s[nt][3] - nmB);
            suA += p0 + p1; suB += p2 + p3;
            int kt = nt >> 1, hi2 = (nt & 1) * 2;
            pah[kt][hi2 + 0] = pk(p0, p1);
            pah[kt][hi2 + 1] = pk(p2, p3);
        }
        suA += __shfl_xor_sync(0xffffffff, suA, 1);
        suA += __shfl_xor_sync(0xffffffff, suA, 2);
        suB += __shfl_xor_sync(0xffffffff, suB, 1);
        suB += __shfl_xor_sync(0xffffffff, suB, 2);
        lA += suA; lB += suB;

        // ---- O += P (vh + vl) (2-term, reordered) ----
        #pragma unroll
        for (int kt = 0; kt < 4; kt++) {
            uint32_t vh4[4][4], vl4[4][4];
            #pragma unroll
            for (int j = 0; j < 4; j++) {
                int row = kt*16 + (lane & 15);
                int col = j*16 + (lane >> 4) * 8;
                ldm4t(vh4[j], sptr(sVh + row*72 + col));
                ldm4t(vl4[j], sptr(sVl + row*72 + col));
            }
            // h-terms across all 8 accumulators
            #pragma unroll
            for (int j = 0; j < 4; j++) {
                uint32_t b0h[2] = {vh4[j][0], vh4[j][1]};
                uint32_t b1h[2] = {vh4[j][2], vh4[j][3]};
                mma16816(o[2*j],   pah[kt], b0h);
                mma16816(o[2*j+1], pah[kt], b1h);
            }
            // l-terms
            #pragma unroll
            for (int j = 0; j < 4; j++) {
                uint32_t b0l[2] = {vl4[j][0], vl4[j][1]};
                uint32_t b1l[2] = {vl4[j][2], vl4[j][3]};
                mma16816(o[2*j],   pah[kt], b0l);
                mma16816(o[2*j+1], pah[kt], b1l);
            }
        }
    }

    // ---- epilogue: normalize, write y as fp16 (hi only) in [B,T,C] ----
    const float iA = 1.0f / lA, iB = 1.0f / lB;
    const int b = bh >> 4, h = bh & 15;
    const int rA = qblk*128 + warp*16 + g;
    const size_t offA = ((size_t)(b * Tt + rA)) * Cc + h * 64;
    const size_t offB = offA + (size_t)8 * Cc;

    #pragma unroll
    for (int nt = 0; nt < 8; nt++) {
        int c = nt*8 + tig*2;
        *(uint32_t*)(g_yh + offA + c) = pk(o[nt][0] * iA, o[nt][1] * iA);
        *(uint32_t*)(g_yh + offB + c) = pk(o[nt][2] * iB, o[nt][3] * iB);
    }
}

// ---------------------------------------------------------------------------
extern "C" void kernel_launch(void* const* d_in, const int* in_sizes, int n_in,
                              void* d_out, int out_size)
{
    const float* x  = (const float*)d_in[0];
    const float* Wq = (const float*)d_in[1];
    const float* bq = (const float*)d_in[2];
    const float* Wk = (const float*)d_in[3];
    const float* bk = (const float*)d_in[4];
    const float* Wv = (const float*)d_in[5];
    const float* bv = (const float*)d_in[6];
    const float* Wp = (const float*)d_in[7];
    const float* bp = (const float*)d_in[8];
    float* out = (float*)d_out;

    __half *xh, *yh, *wh, *wl;
    cudaGetSymbolAddress((void**)&xh, g_xh);
    cudaGetSymbolAddress((void**)&yh, g_yh);
    cudaGetSymbolAddress((void**)&wh, g_wh);
    cudaGetSymbolAddress((void**)&wl, g_wl);

    cudaFuncSetAttribute(gemm_db, cudaFuncAttributeMaxDynamicSharedMemorySize, G_SMEM);
    cudaFuncSetAttribute(attn_mma, cudaFuncAttributeMaxDynamicSharedMemorySize, 2*ABUFSZ);

    // all splits in one launch
    split_all<<<8192 + 4096, 256>>>(x, Wq, Wk, Wv, Wp);

    // fused QKV: one launch, z = 3 (all 2-term)
    const int nw = Cc * Cc;
    dim3 gQKV(Cc / 128, Mrows / 128, 3);     // 8 x 64 x 3
    gemm_db<<<gQKV, 256, G_SMEM>>>(xh, wh, wl, bq, bk, bv, nullptr, 1);

    dim3 gA(Tt / 128, Bm * Hh);
    attn_mma<<<gA, 256, 2*ABUFSZ>>>();

    // out projection (2-term)
    dim3 gO(Cc / 128, Mrows / 128, 1);       // 8 x 64
    gemm_db<<<gO, 256, G_SMEM>>>(yh, wh + 3*nw, wl + 3*nw, bp, bp, bp, out, 0);
}

// round 16
// speedup vs baseline: 1.1480x; 1.1480x over previous
#include <cuda_runtime.h>
#include <cuda_fp16.h>
#include <math.h>
#include <stdint.h>

#define Bm 4
#define Tt 2048
#define Cc 1024
#define Hh 16
#define Dd 64
#define Mrows (Bm*Tt)   // 8192

// ------------------------- device-global scratch (fp16) ---------------------
__device__ __half g_qh[Bm*Hh*Tt*Dd];  // [B,H,T,D] hi (pre-scaled 1/8)
__device__ __half g_kh[Bm*Hh*Tt*Dd];  // hi only
__device__ __half g_vh[Bm*Hh*Tt*Dd];  // hi only

__device__ __half g_xh[Mrows*Cc];
__device__ __half g_yh[Mrows*Cc];      // attention output (hi only)
__device__ __half g_wh[4*Cc*Cc];
__device__ __half g_wl[4*Cc*Cc];

// ---------------------------------------------------------------------------
// fused split kernel: x -> fp16 hi only; weights -> fp16 hi + lo
// ---------------------------------------------------------------------------
__global__ void split_all(const float* __restrict__ x,
                          const float* __restrict__ Wq, const float* __restrict__ Wk,
                          const float* __restrict__ Wv, const float* __restrict__ Wp)
{
    const int bi = blockIdx.x;
    const int tid = threadIdx.x;

    if (bi < 8192) {
        int i = (bi * 256 + tid) * 4;
        float4 v = *(const float4*)(x + i);
        __half2 a; a.x = __float2half_rn(v.x); a.y = __float2half_rn(v.y);
        __half2 b; b.x = __float2half_rn(v.z); b.y = __float2half_rn(v.w);
        *(uint32_t*)(g_xh + i)     = *(uint32_t*)&a;
        *(uint32_t*)(g_xh + i + 2) = *(uint32_t*)&b;
        return;
    }

    int r = bi - 8192;
    int which = r >> 10;
    const float* src = (which == 0) ? Wq : (which == 1) ? Wk : (which == 2) ? Wv : Wp;
    __half* hi = g_wh + (size_t)which * Cc * Cc;
    __half* lo = g_wl + (size_t)which * Cc * Cc;
    int i = (((r & 1023) * 256) + tid) * 4;

    float4 v = *(const float4*)(src + i);
    __half h0 = __float2half_rn(v.x);
    __half h1 = __float2half_rn(v.y);
    __half h2 = __float2half_rn(v.z);
    __half h3 = __float2half_rn(v.w);
    hi[i+0] = h0; hi[i+1] = h1; hi[i+2] = h2; hi[i+3] = h3;
    lo[i+0] = __float2half_rn(v.x - __half2float(h0));
    lo[i+1] = __float2half_rn(v.y - __half2float(h1));
    lo[i+2] = __float2half_rn(v.z - __half2float(h2));
    lo[i+3] = __float2half_rn(v.w - __half2float(h3));
}

// ---------------------------------------------------------------------------
// helpers
// ---------------------------------------------------------------------------
__device__ __forceinline__ uint32_t sptr(const void* p)
{ uint32_t a; asm("{ .reg .u64 t; cvta.to.shared.u64 t, %1; cvt.u32.u64 %0, t; }" : "=r"(a) : "l"(p)); return a; }

__device__ __forceinline__ uint32_t pk(float a, float b)
{
    __half2 t = __floats2half2_rn(a, b);   // a -> low half
    return *(uint32_t*)&t;
}

__device__ __forceinline__ void mma16816(float* c, const uint32_t* a, const uint32_t* b)
{
    asm volatile(
        "mma.sync.aligned.m16n8k16.row.col.f32.f16.f16.f32 "
        "{%0,%1,%2,%3}, {%4,%5,%6,%7}, {%8,%9}, {%0,%1,%2,%3};\n"
        : "+f"(c[0]), "+f"(c[1]), "+f"(c[2]), "+f"(c[3])
        : "r"(a[0]), "r"(a[1]), "r"(a[2]), "r"(a[3]), "r"(b[0]), "r"(b[1]));
}
__device__ __forceinline__ void ldm4(uint32_t* r, uint32_t a)
{
    asm volatile("ldmatrix.sync.aligned.m8n8.x4.shared.b16 {%0,%1,%2,%3}, [%4];"
        : "=r"(r[0]), "=r"(r[1]), "=r"(r[2]), "=r"(r[3]) : "r"(a));
}
__device__ __forceinline__ void ldm4t(uint32_t* r, uint32_t a)
{
    asm volatile("ldmatrix.sync.aligned.m8n8.x4.trans.shared.b16 {%0,%1,%2,%3}, [%4];"
        : "=r"(r[0]), "=r"(r[1]), "=r"(r[2]), "=r"(r[3]) : "r"(a));
}

__device__ __forceinline__ void cpa16(uint32_t dst, const void* src)
{ asm volatile("cp.async.cg.shared.global [%0], [%1], 16;" :: "r"(dst), "l"(src)); }
#define CP_COMMIT() asm volatile("cp.async.commit_group;" ::: "memory")
#define CP_WAIT1()  asm volatile("cp.async.wait_group 1;" ::: "memory")
#define CP_WAIT0()  asm volatile("cp.async.wait_group 0;" ::: "memory")

// ---------------------------------------------------------------------------
// 2-term split-fp16 GEMM: C = Ah @ (Wh + Wl)^T + bias.  (unchanged, at the
// legacy-HMMA issue ceiling.)
// ---------------------------------------------------------------------------
#define PE   40              // pitch in fp16 elements (80 B)
#define STG  30720           // stage bytes (3 arrays x 128 rows x 80 B)
#define G_SMEM (3*STG)       // 92160 B -> 2 CTAs/SM

__global__ __launch_bounds__(256, 2) void gemm_db(
    const __half* __restrict__ Ah,
    const __half* __restrict__ Wh, const __half* __restrict__ Wl,
    const float* __restrict__ b0, const float* __restrict__ b1,
    const float* __restrict__ b2,
    float* __restrict__ outp, int fused)
{
    extern __shared__ char smem[];
    const uint32_t sb = sptr(smem);

    const int which = blockIdx.z;
    const __half* __restrict__ Bh = Wh + (size_t)which * Cc * Cc;
    const __half* __restrict__ Bl = Wl + (size_t)which * Cc * Cc;
    const float* __restrict__ bias = (which == 0) ? b0 : (which == 1) ? b1 : b2;
    const int mode = fused ? which : 3;

    const int tid  = threadIdx.x;
    const int warp = tid >> 5;
    const int lane = tid & 31;
    const int warpM = warp & 3;
    const int warpN = warp >> 2;
    const int gid = lane >> 2;
    const int tig = lane & 3;

    const int rowBase = blockIdx.y * 128;
    const int colBase = blockIdx.x * 128;

    float acc[2][8][4];
    #pragma unroll
    for (int i = 0; i < 2; i++)
        #pragma unroll
        for (int j = 0; j < 8; j++)
            #pragma unroll
            for (int k = 0; k < 4; k++) acc[i][j][k] = 0.0f;

    auto issue = [&](int s, int buf) {
        const int k0 = s * 32;
        const uint32_t bb = sb + buf * STG;
        #pragma unroll
        for (int t = 0; t < 6; t++) {
            int idx = tid + t * 256;
            int row = idx >> 2;
            int part = idx & 3;
            int arr = row >> 7;               // 0:Ah 1:Bh 2:Bl
            int r = row & 127;
            const __half* src = (arr == 0) ? Ah : (arr == 1) ? Bh : Bl;
            int grow = (arr == 0) ? (rowBase + r) : (colBase + r);
            cpa16(bb + arr * 10240 + r * 80 + part * 16,
                  src + (size_t)grow * Cc + k0 + part * 8);
        }
    };

    issue(0, 0);
    CP_COMMIT();
    issue(1, 1);
    CP_COMMIT();

    int bufs = 0;
    for (int s = 0; s < 32; s++) {
        if (s + 1 < 32) { CP_WAIT1(); } else { CP_WAIT0(); }
        __syncthreads();
        if (s + 2 < 32) {
            int b2i = bufs + 2; if (b2i >= 3) b2i -= 3;
            issue(s + 2, b2i);
            CP_COMMIT();
        }

        const char* bb = smem + bufs * STG;
        const __half* sAh = (const __half*)(bb + 0);
        const __half* sBh = (const __half*)(bb + 10240);
        const __half* sBl = (const __half*)(bb + 20480);

        #pragma unroll
        for (int kg = 0; kg < 2; kg++) {
            const int colE = kg * 16 + (lane >> 4) * 8;
            const int arow = warpM * 32 + (lane & 15);

            uint32_t ah0[4], ah1[4];
            ldm4(ah0, sptr(sAh + arow * PE + colE));
            ldm4(ah1, sptr(sAh + (arow + 16) * PE + colE));

            #pragma unroll
            for (int grp = 0; grp < 4; grp++) {
                const int brow = warpN * 64 + grp * 16 + (lane & 15);
                uint32_t th[4], tl[4];
                ldm4(th, sptr(sBh + brow * PE + colE));
                ldm4(tl, sptr(sBl + brow * PE + colE));
                uint32_t b0h[2] = {th[0], th[2]};
                uint32_t b1h[2] = {th[1], th[3]};
                uint32_t b0l[2] = {tl[0], tl[2]};
                uint32_t b1l[2] = {tl[1], tl[3]};
                const int n0 = 2 * grp, n1 = 2 * grp + 1;

                mma16816(acc[0][n0], ah0, b0h);
                mma16816(acc[0][n1], ah0, b1h);
                mma16816(acc[1][n0], ah1, b0h);
                mma16816(acc[1][n1], ah1, b1h);
                mma16816(acc[0][n0], ah0, b0l);
                mma16816(acc[0][n1], ah0, b1l);
                mma16816(acc[1][n0], ah1, b0l);
                mma16816(acc[1][n1], ah1, b1l);
            }
        }
        if (++bufs == 3) bufs = 0;
    }

    // ---- epilogue ----
    if (mode == 3) {
        #pragma unroll
        for (int mi = 0; mi < 2; mi++) {
            #pragma unroll
            for (int ni = 0; ni < 8; ni++) {
                int m0 = rowBase + warpM * 32 + mi * 16 + gid;
                int n0 = colBase + warpN * 64 + ni * 8 + tig * 2;
                #pragma unroll
                for (int e = 0; e < 4; e++) {
                    int m = m0 + ((e >> 1) ? 8 : 0);
                    int n = n0 + (e & 1);
                    outp[(size_t)m * Cc + n] = acc[mi][ni][e] + bias[n];
                }
            }
        }
    } else {
        // QKV: all hi-only now. mode 0 scaled 1/8.
        __half* dh = (mode == 0) ? g_qh : (mode == 1) ? g_kh : g_vh;
        const float sc = (mode == 0) ? 0.125f : 1.0f;
        #pragma unroll
        for (int mi = 0; mi < 2; mi++) {
            #pragma unroll
            for (int ni = 0; ni < 8; ni++) {
                int m0 = rowBase + warpM * 32 + mi * 16 + gid;
                int n0 = colBase + warpN * 64 + ni * 8 + tig * 2;
                #pragma unroll
                for (int half = 0; half < 2; half++) {
                    int m = m0 + half * 8;
                    float v0 = (acc[mi][ni][half*2+0] + bias[n0])   * sc;
                    float v1 = (acc[mi][ni][half*2+1] + bias[n0+1]) * sc;
                    int b = m >> 11, t = m & 2047;
                    int h = n0 >> 6, d = n0 & 63;
                    size_t off = (((size_t)(b * Hh + h)) * Tt + t) * Dd + d;
                    *(uint32_t*)(dh + off) = pk(v0, v1);
                }
            }
        }
    }
}

// ---------------------------------------------------------------------------
// Flash attention, hi-only fp16 K/V, causal, cp.async double-buffer, 2 CTAs/SM.
// S = qh.kh^T.  PV = ph.vh.
// Grid (16, 64), 256 threads (8 warps x 16 q-rows). K/V tiles of 64 keys.
// Buffer: kh 9216 | vh 9216 = 18432 B; 2 buffers. Q staged in buf area first.
// ---------------------------------------------------------------------------
#define ABUFSZ 18432
#define AT_SMEM (2*ABUFSZ)    // 36864

__global__ __launch_bounds__(256, 2) void attn_mma()
{
    extern __shared__ char sm[];
    const uint32_t sbase = sptr(sm);

    const int bh = blockIdx.y;
    const int qblk = (int)gridDim.x - 1 - (int)blockIdx.x;
    const int tid = threadIdx.x;
    const int warp = tid >> 5;
    const int lane = tid & 31;
    const int g = lane >> 2;
    const int tig = lane & 3;

    const size_t base = (size_t)bh * Tt * Dd;

    // ---- stage Q tile (hi only, 128 rows x 64 cols) into buffer area ----
    {
        __half* sQh = (__half*)sm;
        #pragma unroll
        for (int it = 0; it < 4; it++) {
            int idx = tid + it * 256;             // 0..1023
            int r = idx >> 3, c8 = (idx & 7) * 8; // r: 0..127
            size_t goff = base + (size_t)(qblk*128 + r) * Dd + c8;
            *(uint4*)(sQh + r*72 + c8) = *(const uint4*)(g_qh + goff);
        }
    }
    __syncthreads();

    uint32_t qfh[4][4];
    {
        __half* sQh = (__half*)sm;
        int row = warp*16 + (lane & 15);
        #pragma unroll
        for (int kt = 0; kt < 4; kt++) {
            int col = kt*16 + (lane >> 4) * 8;
            ldm4(qfh[kt], sptr(sQh + row*72 + col));
        }
    }
    __syncthreads();

    float o[8][4];
    #pragma unroll
    for (int i = 0; i < 8; i++)
        #pragma unroll
        for (int j = 0; j < 4; j++) o[i][j] = 0.0f;

    float mA = -INFINITY, mB = -INFINITY, lA = 0.0f, lB = 0.0f;
    const int wr0 = qblk*128 + warp*16;
    const int ntiles = 2*qblk + 2;

    // per tile: kh + vh, 64 rows x 128B each = 1024 cpa16, 4 per thread
    auto load_kv = [&](int kb, int buf) {
        const uint32_t bb = sbase + buf * ABUFSZ;
        #pragma unroll
        for (int it = 0; it < 4; it++) {
            int idx = tid + it * 256;             // 0..1023
            int arr = idx >> 9;                   // 0:kh 1:vh
            int rem = idx & 511;
            int r = rem >> 3, c8 = (rem & 7) * 8;
            const __half* src = arr ? g_vh : g_kh;
            size_t goff = base + (size_t)(kb + r) * Dd + c8;
            cpa16(bb + arr * 9216 + (r*72 + c8) * 2, src + goff);
        }
    };

    load_kv(0, 0);
    CP_COMMIT();

    for (int ti = 0; ti < ntiles; ti++) {
        const int kb = ti * 64;
        CP_WAIT0();
        __syncthreads();
        if (ti + 1 < ntiles) { load_kv(kb + 64, (ti + 1) & 1); CP_COMMIT(); }

        const char* bb = sm + (ti & 1) * ABUFSZ;
        const __half* sKh = (const __half*)(bb + 0);
        const __half* sVh = (const __half*)(bb + 9216);

        // ---- S = qh kh^T ----
        float s[8][4];
        #pragma unroll
        for (int i = 0; i < 8; i++)
            #pragma unroll
            for (int j = 0; j < 4; j++) s[i][j] = 0.0f;

        #pragma unroll
        for (int kt = 0; kt < 4; kt++) {
            uint32_t kh4[4][4];
            #pragma unroll
            for (int i = 0; i < 4; i++) {
                int row = i*16 + (lane & 15);
                int col = kt*16 + (lane >> 4) * 8;
                ldm4(kh4[i], sptr(sKh + row*72 + col));
            }
            #pragma unroll
            for (int i = 0; i < 4; i++) {
                uint32_t b0h[2] = {kh4[i][0], kh4[i][2]};
                uint32_t b1h[2] = {kh4[i][1], kh4[i][3]};
                mma16816(s[2*i],   qfh[kt], b0h);
                mma16816(s[2*i+1], qfh[kt], b1h);
            }
        }

        // ---- causal mask ----
        if (kb + 64 > wr0) {
            int rA = wr0 + g, rB = rA + 8;
            #pragma unroll
            for (int nt = 0; nt < 8; nt++) {
                int c0 = kb + nt*8 + tig*2;
                if (c0     > rA) s[nt][0] = -INFINITY;
                if (c0 + 1 > rA) s[nt][1] = -INFINITY;
                if (c0     > rB) s[nt][2] = -INFINITY;
                if (c0 + 1 > rB) s[nt][3] = -INFINITY;
            }
        }

        // ---- online softmax ----
        float ma = -INFINITY, mb = -INFINITY;
        #pragma unroll
        for (int nt = 0; nt < 8; nt++) {
            ma = fmaxf(ma, fmaxf(s[nt][0], s[nt][1]));
            mb = fmaxf(mb, fmaxf(s[nt][2], s[nt][3]));
        }
        ma = fmaxf(ma, __shfl_xor_sync(0xffffffff, ma, 1));
        ma = fmaxf(ma, __shfl_xor_sync(0xffffffff, ma, 2));
        mb = fmaxf(mb, __shfl_xor_sync(0xffffffff, mb, 1));
        mb = fmaxf(mb, __shfl_xor_sync(0xffffffff, mb, 2));

        float nmA = fmaxf(mA, ma), nmB = fmaxf(mB, mb);
        float cA = __expf(mA - nmA), cB = __expf(mB - nmB);
        mA = nmA; mB = nmB;
        lA *= cA; lB *= cB;
        #pragma unroll
        for (int nt = 0; nt < 8; nt++) {
            o[nt][0] *= cA; o[nt][1] *= cA;
            o[nt][2] *= cB; o[nt][3] *= cB;
        }

        // ---- p = exp(s - m), fp16 ----
        uint32_t pah[4][4];
        float suA = 0.0f, suB = 0.0f;
        #pragma unroll
        for (int nt = 0; nt < 8; nt++) {
            float p0 = __expf(s[nt][0] - nmA);
            float p1 = __expf(s[nt][1] - nmA);
            float p2 = __expf(s[nt][2] - nmB);
            float p3 = __expf(s[nt][3] - nmB);
            suA += p0 + p1; suB += p2 + p3;
            int kt = nt >> 1, hi2 = (nt & 1) * 2;
            pah[kt][hi2 + 0] = pk(p0, p1);
            pah[kt][hi2 + 1] = pk(p2, p3);
        }
        suA += __shfl_xor_sync(0xffffffff, suA, 1);
        suA += __shfl_xor_sync(0xffffffff, suA, 2);
        suB += __shfl_xor_sync(0xffffffff, suB, 1);
        suB += __shfl_xor_sync(0xffffffff, suB, 2);
        lA += suA; lB += suB;

        // ---- O += P vh ----
        #pragma unroll
        for (int kt = 0; kt < 4; kt++) {
            uint32_t vh4[4][4];
            #pragma unroll
            for (int j = 0; j < 4; j++) {
                int row = kt*16 + (lane & 15);
                int col = j*16 + (lane >> 4) * 8;
                ldm4t(vh4[j], sptr(sVh + row*72 + col));
            }
            #pragma unroll
            for (int j = 0; j < 4; j++) {
                uint32_t b0h[2] = {vh4[j][0], vh4[j][1]};
                uint32_t b1h[2] = {vh4[j][2], vh4[j][3]};
                mma16816(o[2*j],   pah[kt], b0h);
                mma16816(o[2*j+1], pah[kt], b1h);
            }
        }
    }

    // ---- epilogue: normalize, write y as fp16 (hi only) in [B,T,C] ----
    const float iA = 1.0f / lA, iB = 1.0f / lB;
    const int b = bh >> 4, h = bh & 15;
    const int rA = qblk*128 + warp*16 + g;
    const size_t offA = ((size_t)(b * Tt + rA)) * Cc + h * 64;
    const size_t offB = offA + (size_t)8 * Cc;

    #pragma unroll
    for (int nt = 0; nt < 8; nt++) {
        int c = nt*8 + tig*2;
        *(uint32_t*)(g_yh + offA + c) = pk(o[nt][0] * iA, o[nt][1] * iA);
        *(uint32_t*)(g_yh + offB + c) = pk(o[nt][2] * iB, o[nt][3] * iB);
    }
}

// ---------------------------------------------------------------------------
extern "C" void kernel_launch(void* const* d_in, const int* in_sizes, int n_in,
                              void* d_out, int out_size)
{
    const float* x  = (const float*)d_in[0];
    const float* Wq = (const float*)d_in[1];
    const float* bq = (const float*)d_in[2];
    const float* Wk = (const float*)d_in[3];
    const float* bk = (const float*)d_in[4];
    const float* Wv = (const float*)d_in[5];
    const float* bv = (const float*)d_in[6];
    const float* Wp = (const float*)d_in[7];
    const float* bp = (const float*)d_in[8];
    float* out = (float*)d_out;

    __half *xh, *yh, *wh, *wl;
    cudaGetSymbolAddress((void**)&xh, g_xh);
    cudaGetSymbolAddress((void**)&yh, g_yh);
    cudaGetSymbolAddress((void**)&wh, g_wh);
    cudaGetSymbolAddress((void**)&wl, g_wl);

    cudaFuncSetAttribute(gemm_db, cudaFuncAttributeMaxDynamicSharedMemorySize, G_SMEM);
    cudaFuncSetAttribute(attn_mma, cudaFuncAttributeMaxDynamicSharedMemorySize, AT_SMEM);

    // all splits in one launch
    split_all<<<8192 + 4096, 256>>>(x, Wq, Wk, Wv, Wp);

    // fused QKV: one launch, z = 3 (all 2-term)
    const int nw = Cc * Cc;
    dim3 gQKV(Cc / 128, Mrows / 128, 3);     // 8 x 64 x 3
    gemm_db<<<gQKV, 256, G_SMEM>>>(xh, wh, wl, bq, bk, bv, nullptr, 1);

    dim3 gA(Tt / 128, Bm * Hh);
    attn_mma<<<gA, 256, AT_SMEM>>>();

    // out projection (2-term)
    dim3 gO(Cc / 128, Mrows / 128, 1);       // 8 x 64
    gemm_db<<<gO, 256, G_SMEM>>>(yh, wh + 3*nw, wl + 3*nw, bp, bp, bp, out, 0);
}

// round 17
// speedup vs baseline: 1.6766x; 1.4604x over previous
#include <cuda_runtime.h>
#include <cuda_fp16.h>
#include <math.h>
#include <stdint.h>

#define Bm 4
#define Tt 2048
#define Cc 1024
#define Hh 16
#define Dd 64
#define Mrows (Bm*Tt)   // 8192

// ------------------------- device-global scratch (fp16, all hi-only) --------
__device__ __half g_qh[Bm*Hh*Tt*Dd];  // [B,H,T,D] (pre-scaled 1/8)
__device__ __half g_kh[Bm*Hh*Tt*Dd];
__device__ __half g_vh[Bm*Hh*Tt*Dd];

__device__ __half g_xh[Mrows*Cc];
__device__ __half g_yh[Mrows*Cc];      // attention output
__device__ __half g_wh[4*Cc*Cc];

// ---------------------------------------------------------------------------
// fused split kernel: everything -> fp16 (round-to-nearest)
// ---------------------------------------------------------------------------
__global__ void split_all(const float* __restrict__ x,
                          const float* __restrict__ Wq, const float* __restrict__ Wk,
                          const float* __restrict__ Wv, const float* __restrict__ Wp)
{
    const int bi = blockIdx.x;
    const int tid = threadIdx.x;

    const float* src;
    __half* dst;
    int i;
    if (bi < 8192) {
        src = x; dst = g_xh;
        i = (bi * 256 + tid) * 4;
    } else {
        int r = bi - 8192;
        int which = r >> 10;
        src = (which == 0) ? Wq : (which == 1) ? Wk : (which == 2) ? Wv : Wp;
        dst = g_wh + (size_t)which * Cc * Cc;
        i = (((r & 1023) * 256) + tid) * 4;
    }

    float4 v = *(const float4*)(src + i);
    __half2 a; a.x = __float2half_rn(v.x); a.y = __float2half_rn(v.y);
    __half2 b; b.x = __float2half_rn(v.z); b.y = __float2half_rn(v.w);
    *(uint32_t*)(dst + i)     = *(uint32_t*)&a;
    *(uint32_t*)(dst + i + 2) = *(uint32_t*)&b;
}

// ---------------------------------------------------------------------------
// helpers
// ---------------------------------------------------------------------------
__device__ __forceinline__ uint32_t sptr(const void* p)
{ uint32_t a; asm("{ .reg .u64 t; cvta.to.shared.u64 t, %1; cvt.u32.u64 %0, t; }" : "=r"(a) : "l"(p)); return a; }

__device__ __forceinline__ uint32_t pk(float a, float b)
{
    __half2 t = __floats2half2_rn(a, b);   // a -> low half
    return *(uint32_t*)&t;
}

__device__ __forceinline__ void mma16816(float* c, const uint32_t* a, const uint32_t* b)
{
    asm volatile(
        "mma.sync.aligned.m16n8k16.row.col.f32.f16.f16.f32 "
        "{%0,%1,%2,%3}, {%4,%5,%6,%7}, {%8,%9}, {%0,%1,%2,%3};\n"
        : "+f"(c[0]), "+f"(c[1]), "+f"(c[2]), "+f"(c[3])
        : "r"(a[0]), "r"(a[1]), "r"(a[2]), "r"(a[3]), "r"(b[0]), "r"(b[1]));
}
__device__ __forceinline__ void ldm4(uint32_t* r, uint32_t a)
{
    asm volatile("ldmatrix.sync.aligned.m8n8.x4.shared.b16 {%0,%1,%2,%3}, [%4];"
        : "=r"(r[0]), "=r"(r[1]), "=r"(r[2]), "=r"(r[3]) : "r"(a));
}
__device__ __forceinline__ void ldm4t(uint32_t* r, uint32_t a)
{
    asm volatile("ldmatrix.sync.aligned.m8n8.x4.trans.shared.b16 {%0,%1,%2,%3}, [%4];"
        : "=r"(r[0]), "=r"(r[1]), "=r"(r[2]), "=r"(r[3]) : "r"(a));
}

__device__ __forceinline__ void cpa16(uint32_t dst, const void* src)
{ asm volatile("cp.async.cg.shared.global [%0], [%1], 16;" :: "r"(dst), "l"(src)); }
#define CP_COMMIT() asm volatile("cp.async.commit_group;" ::: "memory")
#define CP_WAIT1()  asm volatile("cp.async.wait_group 1;" ::: "memory")
#define CP_WAIT0()  asm volatile("cp.async.wait_group 0;" ::: "memory")

// ---------------------------------------------------------------------------
// fp16 hi-only GEMM: C = Ah @ Wh^T + bias.
// K-stage 32, 3-stage cp.async ring, ldmatrix frags, 2 CTAs/SM.
// CTA tile 128(M) x 128(N), 8 warps (4M x 2N), warp 32x64.
// Stage: 2 arrays (Ah, Bh) x 128 rows x 80B pitch = 20480 B; 3 stages = 60 KB.
// fused=1: blockIdx.z selects Wq/Wk/Wv -> fp16 epilogue to QKV [B,H,T,D]
//   (mode 0 scaled 1/8).  fused=0: fp32 linear to outp.
// ---------------------------------------------------------------------------
#define PE   40              // pitch in fp16 elements (80 B)
#define STG  20480           // stage bytes (2 arrays x 128 rows x 80 B)
#define G_SMEM (3*STG)       // 61440 B -> 2 CTAs/SM

__global__ __launch_bounds__(256, 2) void gemm_db(
    const __half* __restrict__ Ah,
    const __half* __restrict__ Wh,
    const float* __restrict__ b0, const float* __restrict__ b1,
    const float* __restrict__ b2,
    float* __restrict__ outp, int fused)
{
    extern __shared__ char smem[];
    const uint32_t sb = sptr(smem);

    const int which = blockIdx.z;
    const __half* __restrict__ Bh = Wh + (size_t)which * Cc * Cc;
    const float* __restrict__ bias = (which == 0) ? b0 : (which == 1) ? b1 : b2;
    const int mode = fused ? which : 3;

    const int tid  = threadIdx.x;
    const int warp = tid >> 5;
    const int lane = tid & 31;
    const int warpM = warp & 3;
    const int warpN = warp >> 2;
    const int gid = lane >> 2;
    const int tig = lane & 3;

    const int rowBase = blockIdx.y * 128;
    const int colBase = blockIdx.x * 128;

    float acc[2][8][4];
    #pragma unroll
    for (int i = 0; i < 2; i++)
        #pragma unroll
        for (int j = 0; j < 8; j++)
            #pragma unroll
            for (int k = 0; k < 4; k++) acc[i][j][k] = 0.0f;

    // stage loader: 256 rows x 64B = 1024 cp.async of 16B, 4 per thread
    auto issue = [&](int s, int buf) {
        const int k0 = s * 32;
        const uint32_t bb = sb + buf * STG;
        #pragma unroll
        for (int t = 0; t < 4; t++) {
            int idx = tid + t * 256;          // 0..1023
            int row = idx >> 2;               // 0..255
            int part = idx & 3;
            int arr = row >> 7;               // 0:Ah 1:Bh
            int r = row & 127;
            const __half* src = arr ? Bh : Ah;
            int grow = arr ? (colBase + r) : (rowBase + r);
            cpa16(bb + arr * 10240 + r * 80 + part * 16,
                  src + (size_t)grow * Cc + k0 + part * 8);
        }
    };

    issue(0, 0);
    CP_COMMIT();
    issue(1, 1);
    CP_COMMIT();

    int bufs = 0;
    for (int s = 0; s < 32; s++) {
        if (s + 1 < 32) { CP_WAIT1(); } else { CP_WAIT0(); }
        __syncthreads();
        if (s + 2 < 32) {
            int b2i = bufs + 2; if (b2i >= 3) b2i -= 3;
            issue(s + 2, b2i);
            CP_COMMIT();
        }

        const char* bb = smem + bufs * STG;
        const __half* sAh = (const __half*)(bb + 0);
        const __half* sBh = (const __half*)(bb + 10240);

        #pragma unroll
        for (int kg = 0; kg < 2; kg++) {
            const int colE = kg * 16 + (lane >> 4) * 8;
            const int arow = warpM * 32 + (lane & 15);

            uint32_t ah0[4], ah1[4];
            ldm4(ah0, sptr(sAh + arow * PE + colE));
            ldm4(ah1, sptr(sAh + (arow + 16) * PE + colE));

            #pragma unroll
            for (int grp = 0; grp < 4; grp++) {
                const int brow = warpN * 64 + grp * 16 + (lane & 15);
                uint32_t th[4];
                ldm4(th, sptr(sBh + brow * PE + colE));
                uint32_t b0h[2] = {th[0], th[2]};
                uint32_t b1h[2] = {th[1], th[3]};
                const int n0 = 2 * grp, n1 = 2 * grp + 1;

                mma16816(acc[0][n0], ah0, b0h);
                mma16816(acc[0][n1], ah0, b1h);
                mma16816(acc[1][n0], ah1, b0h);
                mma16816(acc[1][n1], ah1, b1h);
            }
        }
        if (++bufs == 3) bufs = 0;
    }

    // ---- epilogue ----
    if (mode == 3) {
        #pragma unroll
        for (int mi = 0; mi < 2; mi++) {
            #pragma unroll
            for (int ni = 0; ni < 8; ni++) {
                int m0 = rowBase + warpM * 32 + mi * 16 + gid;
                int n0 = colBase + warpN * 64 + ni * 8 + tig * 2;
                #pragma unroll
                for (int e = 0; e < 4; e++) {
                    int m = m0 + ((e >> 1) ? 8 : 0);
                    int n = n0 + (e & 1);
                    outp[(size_t)m * Cc + n] = acc[mi][ni][e] + bias[n];
                }
            }
        }
    } else {
        __half* dh = (mode == 0) ? g_qh : (mode == 1) ? g_kh : g_vh;
        const float sc = (mode == 0) ? 0.125f : 1.0f;
        #pragma unroll
        for (int mi = 0; mi < 2; mi++) {
            #pragma unroll
            for (int ni = 0; ni < 8; ni++) {
                int m0 = rowBase + warpM * 32 + mi * 16 + gid;
                int n0 = colBase + warpN * 64 + ni * 8 + tig * 2;
                #pragma unroll
                for (int half = 0; half < 2; half++) {
                    int m = m0 + half * 8;
                    float v0 = (acc[mi][ni][half*2+0] + bias[n0])   * sc;
                    float v1 = (acc[mi][ni][half*2+1] + bias[n0+1]) * sc;
                    int b = m >> 11, t = m & 2047;
                    int h = n0 >> 6, d = n0 & 63;
                    size_t off = (((size_t)(b * Hh + h)) * Tt + t) * Dd + d;
                    *(uint32_t*)(dh + off) = pk(v0, v1);
                }
            }
        }
    }
}

// ---------------------------------------------------------------------------
// Flash attention, hi-only fp16, causal, cp.async double-buffer, 2 CTAs/SM.
// (unchanged from R16)
// ---------------------------------------------------------------------------
#define ABUFSZ 18432
#define AT_SMEM (2*ABUFSZ)    // 36864

__global__ __launch_bounds__(256, 2) void attn_mma()
{
    extern __shared__ char sm[];
    const uint32_t sbase = sptr(sm);

    const int bh = blockIdx.y;
    const int qblk = (int)gridDim.x - 1 - (int)blockIdx.x;
    const int tid = threadIdx.x;
    const int warp = tid >> 5;
    const int lane = tid & 31;
    const int g = lane >> 2;
    const int tig = lane & 3;

    const size_t base = (size_t)bh * Tt * Dd;

    // ---- stage Q tile (128 rows x 64 cols) into buffer area ----
    {
        __half* sQh = (__half*)sm;
        #pragma unroll
        for (int it = 0; it < 4; it++) {
            int idx = tid + it * 256;
            int r = idx >> 3, c8 = (idx & 7) * 8;
            size_t goff = base + (size_t)(qblk*128 + r) * Dd + c8;
            *(uint4*)(sQh + r*72 + c8) = *(const uint4*)(g_qh + goff);
        }
    }
    __syncthreads();

    uint32_t qfh[4][4];
    {
        __half* sQh = (__half*)sm;
        int row = warp*16 + (lane & 15);
        #pragma unroll
        for (int kt = 0; kt < 4; kt++) {
            int col = kt*16 + (lane >> 4) * 8;
            ldm4(qfh[kt], sptr(sQh + row*72 + col));
        }
    }
    __syncthreads();

    float o[8][4];
    #pragma unroll
    for (int i = 0; i < 8; i++)
        #pragma unroll
        for (int j = 0; j < 4; j++) o[i][j] = 0.0f;

    float mA = -INFINITY, mB = -INFINITY, lA = 0.0f, lB = 0.0f;
    const int wr0 = qblk*128 + warp*16;
    const int ntiles = 2*qblk + 2;

    auto load_kv = [&](int kb, int buf) {
        const uint32_t bb = sbase + buf * ABUFSZ;
        #pragma unroll
        for (int it = 0; it < 4; it++) {
            int idx = tid + it * 256;
            int arr = idx >> 9;                   // 0:kh 1:vh
            int rem = idx & 511;
            int r = rem >> 3, c8 = (rem & 7) * 8;
            const __half* src = arr ? g_vh : g_kh;
            size_t goff = base + (size_t)(kb + r) * Dd + c8;
            cpa16(bb + arr * 9216 + (r*72 + c8) * 2, src + goff);
        }
    };

    load_kv(0, 0);
    CP_COMMIT();

    for (int ti = 0; ti < ntiles; ti++) {
        const int kb = ti * 64;
        CP_WAIT0();
        __syncthreads();
        if (ti + 1 < ntiles) { load_kv(kb + 64, (ti + 1) & 1); CP_COMMIT(); }

        const char* bb = sm + (ti & 1) * ABUFSZ;
        const __half* sKh = (const __half*)(bb + 0);
        const __half* sVh = (const __half*)(bb + 9216);

        // ---- S = qh kh^T ----
        float s[8][4];
        #pragma unroll
        for (int i = 0; i < 8; i++)
            #pragma unroll
            for (int j = 0; j < 4; j++) s[i][j] = 0.0f;

        #pragma unroll
        for (int kt = 0; kt < 4; kt++) {
            uint32_t kh4[4][4];
            #pragma unroll
            for (int i = 0; i < 4; i++) {
                int row = i*16 + (lane & 15);
                int col = kt*16 + (lane >> 4) * 8;
                ldm4(kh4[i], sptr(sKh + row*72 + col));
            }
            #pragma unroll
            for (int i = 0; i < 4; i++) {
                uint32_t b0h[2] = {kh4[i][0], kh4[i][2]};
                uint32_t b1h[2] = {kh4[i][1], kh4[i][3]};
                mma16816(s[2*i],   qfh[kt], b0h);
                mma16816(s[2*i+1], qfh[kt], b1h);
            }
        }

        // ---- causal mask ----
        if (kb + 64 > wr0) {
            int rA = wr0 + g, rB = rA + 8;
            #pragma unroll
            for (int nt = 0; nt < 8; nt++) {
                int c0 = kb + nt*8 + tig*2;
                if (c0     > rA) s[nt][0] = -INFINITY;
                if (c0 + 1 > rA) s[nt][1] = -INFINITY;
                if (c0     > rB) s[nt][2] = -INFINITY;
                if (c0 + 1 > rB) s[nt][3] = -INFINITY;
            }
        }

        // ---- online softmax ----
        float ma = -INFINITY, mb = -INFINITY;
        #pragma unroll
        for (int nt = 0; nt < 8; nt++) {
            ma = fmaxf(ma, fmaxf(s[nt][0], s[nt][1]));
            mb = fmaxf(mb, fmaxf(s[nt][2], s[nt][3]));
        }
        ma = fmaxf(ma, __shfl_xor_sync(0xffffffff, ma, 1));
        ma = fmaxf(ma, __shfl_xor_sync(0xffffffff, ma, 2));
        mb = fmaxf(mb, __shfl_xor_sync(0xffffffff, mb, 1));
        mb = fmaxf(mb, __shfl_xor_sync(0xffffffff, mb, 2));

        float nmA = fmaxf(mA, ma), nmB = fmaxf(mB, mb);
        float cA = __expf(mA - nmA), cB = __expf(mB - nmB);
        mA = nmA; mB = nmB;
        lA *= cA; lB *= cB;
        #pragma unroll
        for (int nt = 0; nt < 8; nt++) {
            o[nt][0] *= cA; o[nt][1] *= cA;
            o[nt][2] *= cB; o[nt][3] *= cB;
        }

        // ---- p = exp(s - m), fp16 ----
        uint32_t pah[4][4];
        float suA = 0.0f, suB = 0.0f;
        #pragma unroll
        for (int nt = 0; nt < 8; nt++) {
            float p0 = __expf(s[nt][0] - nmA);
            float p1 = __expf(s[nt][1] - nmA);
            float p2 = __expf(s[nt][2] - nmB);
            float p3 = __expf(s[nt][3] - nmB);
            suA += p0 + p1; suB += p2 + p3;
            int kt = nt >> 1, hi2 = (nt & 1) * 2;
            pah[kt][hi2 + 0] = pk(p0, p1);
            pah[kt][hi2 + 1] = pk(p2, p3);
        }
        suA += __shfl_xor_sync(0xffffffff, suA, 1);
        suA += __shfl_xor_sync(0xffffffff, suA, 2);
        suB += __shfl_xor_sync(0xffffffff, suB, 1);
        suB += __shfl_xor_sync(0xffffffff, suB, 2);
        lA += suA; lB += suB;

        // ---- O += P vh ----
        #pragma unroll
        for (int kt = 0; kt < 4; kt++) {
            uint32_t vh4[4][4];
            #pragma unroll
            for (int j = 0; j < 4; j++) {
                int row = kt*16 + (lane & 15);
                int col = j*16 + (lane >> 4) * 8;
                ldm4t(vh4[j], sptr(sVh + row*72 + col));
            }
            #pragma unroll
            for (int j = 0; j < 4; j++) {
                uint32_t b0h[2] = {vh4[j][0], vh4[j][1]};
                uint32_t b1h[2] = {vh4[j][2], vh4[j][3]};
                mma16816(o[2*j],   pah[kt], b0h);
                mma16816(o[2*j+1], pah[kt], b1h);
            }
        }
    }

    // ---- epilogue: normalize, write y as fp16 in [B,T,C] ----
    const float iA = 1.0f / lA, iB = 1.0f / lB;
    const int b = bh >> 4, h = bh & 15;
    const int rA = qblk*128 + warp*16 + g;
    const size_t offA = ((size_t)(b * Tt + rA)) * Cc + h * 64;
    const size_t offB = offA + (size_t)8 * Cc;

    #pragma unroll
    for (int nt = 0; nt < 8; nt++) {
        int c = nt*8 + tig*2;
        *(uint32_t*)(g_yh + offA + c) = pk(o[nt][0] * iA, o[nt][1] * iA);
        *(uint32_t*)(g_yh + offB + c) = pk(o[nt][2] * iB, o[nt][3] * iB);
    }
}

// ---------------------------------------------------------------------------
extern "C" void kernel_launch(void* const* d_in, const int* in_sizes, int n_in,
                              void* d_out, int out_size)
{
    const float* x  = (const float*)d_in[0];
    const float* Wq = (const float*)d_in[1];
    const float* bq = (const float*)d_in[2];
    const float* Wk = (const float*)d_in[3];
    const float* bk = (const float*)d_in[4];
    const float* Wv = (const float*)d_in[5];
    const float* bv = (const float*)d_in[6];
    const float* Wp = (const float*)d_in[7];
    const float* bp = (const float*)d_in[8];
    float* out = (float*)d_out;

    __half *xh, *yh, *wh;
    cudaGetSymbolAddress((void**)&xh, g_xh);
    cudaGetSymbolAddress((void**)&yh, g_yh);
    cudaGetSymbolAddress((void**)&wh, g_wh);

    cudaFuncSetAttribute(gemm_db, cudaFuncAttributeMaxDynamicSharedMemorySize, G_SMEM);
    cudaFuncSetAttribute(attn_mma, cudaFuncAttributeMaxDynamicSharedMemorySize, AT_SMEM);

    // all splits in one launch
    split_all<<<8192 + 4096, 256>>>(x, Wq, Wk, Wv, Wp);

    // fused QKV: one launch, z = 3 (hi-only)
    const int nw = Cc * Cc;
    dim3 gQKV(Cc / 128, Mrows / 128, 3);     // 8 x 64 x 3
    gemm_db<<<gQKV, 256, G_SMEM>>>(xh, wh, bq, bk, bv, nullptr, 1);

    dim3 gA(Tt / 128, Bm * Hh);
    attn_mma<<<gA, 256, AT_SMEM>>>();

    // out projection (hi-only)
    dim3 gO(Cc / 128, Mrows / 128, 1);       // 8 x 64
    gemm_db<<<gO, 256, G_SMEM>>>(yh, wh + 3*nw, bp, bp, bp, out, 0);
}